// round 10
// baseline (speedup 1.0000x reference)
#include <cuda_runtime.h>

#define MAXD 365
#define NREP 8            // histogram replicas (warp>>1 selects)
#define RSTR 369          // replica stride (mod 32 = 17: decorrelates banks)
#define NTHR 512
#define NBLK 592          // 4 blocks/SM * 148 SMs
#define NWRP (NTHR / 32)

__device__ float    g_S[MAXD];      // sum exp(clip(y)) per bucket
__device__ unsigned g_M[MAXD];      // event count per bucket
__device__ float    g_sey;          // sum e_i * y_i
__device__ unsigned g_done;         // finalize ticket

__device__ __forceinline__ void body4(const float4& y, const int4& d, const int4& e,
                                      float* sS, unsigned* sMh, int rb, float& sey)
{
    #pragma unroll
    for (int k = 0; k < 4; k++) {
        float yy = (&y.x)[k];
        int   dd = (&d.x)[k];
        dd = (dd < 0) ? 0 : ((dd >= MAXD) ? MAXD - 1 : dd);
        int   ec = (&e.x)[k];
        float x  = fminf(fmaxf(yy, -20.f), 20.f);
        atomicAdd(&sS[rb + dd], __expf(x));
        if (ec) {
            atomicAdd(&sMh[rb + dd], 1u);
            sey += yy;
        }
    }
}

__global__ void __launch_bounds__(NTHR, 4)
cox_rep_kernel(const float* __restrict__ pred,
               const int*   __restrict__ dur,
               const int*   __restrict__ ev,
               float* __restrict__ out,
               int n)
{
    __shared__ float    sS[NREP * RSTR];    // replicated exp hist (reused in finalize)
    __shared__ unsigned sMh[NREP * RSTR];   // replicated event hist
    __shared__ float    wA[NWRP];
    __shared__ unsigned sIsLast;

    const int t    = threadIdx.x;
    const int lane = t & 31, wid = t >> 5;
    const int rb   = ((wid >> 1) & (NREP - 1)) * RSTR;
    const int nv   = n >> 2;
    const int stride = NBLK * NTHR;

    for (int i = t; i < NREP * RSTR; i += NTHR) { sS[i] = 0.f; sMh[i] = 0u; }
    __syncthreads();

    float sey = 0.f;

    // ==== single pass, 2-deep load batching (6 LDG.128 in flight) ====
    {
        const float4* p4 = (const float4*)pred;
        const int4*   d4 = (const int4*)dur;
        const int4*   e4 = (const int4*)ev;
        int i = blockIdx.x * NTHR + t;
        for (; i + stride < nv; i += 2 * stride) {
            int j = i + stride;
            float4 yA = p4[i];
            int4   dA = d4[i];
            int4   eA = e4[i];
            float4 yB = p4[j];
            int4   dB = d4[j];
            int4   eB = e4[j];
            body4(yA, dA, eA, sS, sMh, rb, sey);
            body4(yB, dB, eB, sS, sMh, rb, sey);
        }
        if (i < nv) {
            float4 yA = p4[i];
            int4   dA = d4[i];
            int4   eA = e4[i];
            body4(yA, dA, eA, sS, sMh, rb, sey);
        }
        for (int s = (nv << 2) + blockIdx.x * NTHR + t; s < n; s += stride) {
            float yy = pred[s];
            int   dd = dur[s];
            dd = (dd < 0) ? 0 : ((dd >= MAXD) ? MAXD - 1 : dd);
            int   ec = ev[s];
            float x  = fminf(fmaxf(yy, -20.f), 20.f);
            atomicAdd(&sS[rb + dd], __expf(x));
            if (ec) { atomicAdd(&sMh[rb + dd], 1u); sey += yy; }
        }
    }

    // block-reduce sey -> global
    #pragma unroll
    for (int o = 16; o; o >>= 1)
        sey += __shfl_down_sync(0xffffffffu, sey, o);
    if (lane == 0) wA[wid] = sey;
    __syncthreads();
    if (t == 0) {
        float a = 0.f;
        #pragma unroll
        for (int w = 0; w < NWRP; w++) a += wA[w];
        atomicAdd(&g_sey, a);
    }

    // flush: sum replicas, one global atomic per non-empty bucket
    for (int i = t; i < MAXD; i += NTHR) {
        float    s = 0.f;
        unsigned m = 0u;
        #pragma unroll
        for (int r = 0; r < NREP; r++) {
            s += sS[r * RSTR + i];
            m += sMh[r * RSTR + i];
        }
        if (s != 0.f) atomicAdd(&g_S[i], s);
        if (m)        atomicAdd(&g_M[i], m);
    }

    // ================= last-block finalize =================
    __threadfence();
    if (t == 0) {
        unsigned ticket = atomicAdd(&g_done, 1u);
        sIsLast = (ticket == (unsigned)(NBLK - 1)) ? 1u : 0u;
    }
    __syncthreads();
    if (!sIsLast) return;

    float*    scan = sS;
    float*    redF = sS + 1024;
    unsigned* redN = sMh;

    float    s = (t < MAXD) ? __ldcg(&g_S[t]) : 0.f;
    unsigned m = (t < MAXD) ? __ldcg(&g_M[t]) : 0u;
    __syncthreads();
    scan[t] = s;
    __syncthreads();

    // Hillis-Steele inclusive suffix scan: scan[t] = sum_{j>=t} S[j]
    #pragma unroll
    for (int off = 1; off < NTHR; off <<= 1) {
        float v = (t + off < NTHR) ? scan[t + off] : 0.f;
        __syncthreads();
        scan[t] += v;
        __syncthreads();
    }

    float lg = logf(fmaxf(scan[t], 1e-12f));
    __syncthreads();
    scan[t] = (t < MAXD) ? lg : 0.f;        // logR LUT (dead corner)
    redF[t] = (float)m * ((t < MAXD) ? lg : 0.f);
    redN[t] = m;
    __syncthreads();

    #pragma unroll
    for (int off = NTHR / 2; off; off >>= 1) {
        if (t < off) {
            redF[t] += redF[t + off];
            redN[t] += redN[t + off];
        }
        __syncthreads();
    }

    unsigned nev = redN[0];

    if (nev > 0u) {
        if (t == 0) {
            float total_ll = __ldcg(&g_sey) - redF[0];
            out[0] = -total_ll / fmaxf((float)nev, 1.f);
        }
    } else {
        // dead-in-practice corner: e.sum()==0 -> e := 1e-8 everywhere
        float slr = 0.f, syl = 0.f;
        for (int i = t; i < n; i += NTHR) {
            int dd = dur[i];
            dd = (dd < 0) ? 0 : ((dd >= MAXD) ? MAXD - 1 : dd);
            slr += scan[dd];
            syl += pred[i];
        }
        #pragma unroll
        for (int o = 16; o; o >>= 1) {
            slr += __shfl_down_sync(0xffffffffu, slr, o);
            syl += __shfl_down_sync(0xffffffffu, syl, o);
        }
        if (lane == 0) { wA[wid] = slr; redF[wid] = syl; }
        __syncthreads();
        if (t == 0) {
            float tot = 0.f, sy = 0.f;
            #pragma unroll
            for (int w = 0; w < NWRP; w++) { tot += wA[w]; sy += redF[w]; }
            float total_ll = 1e-8f * (sy - tot);
            float n_events = fmaxf(1e-8f * (float)n, 1.f);
            out[0] = -total_ll / n_events;
        }
    }

    // re-zero globals for next graph replay
    __syncthreads();
    for (int i = t; i < MAXD; i += NTHR) { g_S[i] = 0.f; g_M[i] = 0u; }
    if (t == 0) { g_sey = 0.f; g_done = 0u; }
}

extern "C" void kernel_launch(void* const* d_in, const int* in_sizes, int n_in,
                              void* d_out, int out_size)
{
    const float* pred = (const float*)d_in[0];
    const int*   dur  = (const int*)d_in[1];
    const int*   ev   = (const int*)d_in[2];
    int n = in_sizes[0];

    cox_rep_kernel<<<NBLK, NTHR>>>(pred, dur, ev, (float*)d_out, n);
}